// round 6
// baseline (speedup 1.0000x reference)
#include <cuda_runtime.h>
#include <math.h>

// Problem constants
#define B_DIM 64
#define S_DIM 4096
#define C_DIM 128
#define N2 2048          // half-length complex FFT size
#define NT 256
#define TOPK 64

// Twiddle table in global: g_tw[t] = (cos(pi t/2048), sin(pi t/2048))
__device__ float2 g_tw[N2];

__device__ __forceinline__ float2 cmul(float2 a, float2 b) {
    return make_float2(a.x * b.x - a.y * b.y, a.x * b.y + a.y * b.x);
}

// Bank swizzle: bijective on [0, 2048); makes all Stockham radix-4
// scatter patterns (stride-4, 16g+r blocks, consecutive) conflict-free.
__device__ __forceinline__ int SW(int i) { return i ^ (i >> 2); }

// Bit-exact mag^2 (used for both the ranking values and the tie re-check).
__device__ __forceinline__ unsigned mag2u(float2 x) {
    return __float_as_uint(__fadd_rn(__fmul_rn(x.x, x.x), __fmul_rn(x.y, x.y)));
}

// ---------------------------------------------------------------------------
__global__ void __launch_bounds__(256) init_tw_kernel() {
    int t = blockIdx.x * 256 + threadIdx.x;
    float s, c;
    sincospif((float)t * (1.0f / 2048.0f), &s, &c);
    g_tw[t] = make_float2(c, s);
}

// ---------------------------------------------------------------------------
// Radix-4 Stockham stage (generic, smem->smem, swizzled). Twiddles from global.
// ---------------------------------------------------------------------------
template<int L, bool INV>
__device__ __forceinline__ void r4_stage(const float2* __restrict__ src,
                                         float2* __restrict__ dst,
                                         const float2* __restrict__ TW) {
    const int tid = threadIdx.x;
#pragma unroll
    for (int ii = 0; ii < 2; ++ii) {
        int i = tid + ii * NT;
        int k = i & (L - 1);
        int u = i - k;
        float2 a0 = src[SW(i)];
        float2 a1 = src[SW(i + 512)];
        float2 a2 = src[SW(i + 1024)];
        float2 a3 = src[SW(i + 1536)];
        float2 t0 = make_float2(a0.x + a2.x, a0.y + a2.y);
        float2 t1 = make_float2(a0.x - a2.x, a0.y - a2.y);
        float2 t2 = make_float2(a1.x + a3.x, a1.y + a3.y);
        float2 t3 = make_float2(a1.x - a3.x, a1.y - a3.y);
        float2 b0 = make_float2(t0.x + t2.x, t0.y + t2.y);
        float2 b2 = make_float2(t0.x - t2.x, t0.y - t2.y);
        float2 b1, b3;
        if (!INV) {
            b1 = make_float2(t1.x + t3.y, t1.y - t3.x);   // t1 - i t3
            b3 = make_float2(t1.x - t3.y, t1.y + t3.x);   // t1 + i t3
        } else {
            b1 = make_float2(t1.x - t3.y, t1.y + t3.x);
            b3 = make_float2(t1.x + t3.y, t1.y - t3.x);
        }
        float2 w1 = TW[2 * u];
        if (!INV) w1.y = -w1.y;
        float2 w2 = cmul(w1, w1);
        float2 w3 = cmul(w1, w2);
        int o = 4 * u + k;
        dst[SW(o)]         = b0;
        dst[SW(o + L)]     = cmul(b1, w1);
        dst[SW(o + 2 * L)] = cmul(b2, w2);
        dst[SW(o + 3 * L)] = cmul(b3, w3);
    }
}

// First forward stage (L=1), reading directly from the strided gmem channel:
// x(s) = gch[s * C_DIM];  z[n] = x(2n) + i x(2n+1)
__device__ __forceinline__ void r4_first_fwd_gmem(const float* __restrict__ gch,
                                                  float2* __restrict__ dst,
                                                  const float2* __restrict__ TW) {
    const int tid = threadIdx.x;
#pragma unroll
    for (int ii = 0; ii < 2; ++ii) {
        int i = tid + ii * NT;
        float2 a0, a1, a2, a3;
        a0.x = gch[(2 * i)          * C_DIM]; a0.y = gch[(2 * i + 1)    * C_DIM];
        a1.x = gch[(2 * i + 1024)   * C_DIM]; a1.y = gch[(2 * i + 1025) * C_DIM];
        a2.x = gch[(2 * i + 2048)   * C_DIM]; a2.y = gch[(2 * i + 2049) * C_DIM];
        a3.x = gch[(2 * i + 3072)   * C_DIM]; a3.y = gch[(2 * i + 3073) * C_DIM];
        float2 t0 = make_float2(a0.x + a2.x, a0.y + a2.y);
        float2 t1 = make_float2(a0.x - a2.x, a0.y - a2.y);
        float2 t2 = make_float2(a1.x + a3.x, a1.y + a3.y);
        float2 t3 = make_float2(a1.x - a3.x, a1.y - a3.y);
        float2 b0 = make_float2(t0.x + t2.x, t0.y + t2.y);
        float2 b2 = make_float2(t0.x - t2.x, t0.y - t2.y);
        float2 b1 = make_float2(t1.x + t3.y, t1.y - t3.x);
        float2 b3 = make_float2(t1.x - t3.y, t1.y + t3.x);
        float2 w1 = TW[2 * i]; w1.y = -w1.y;
        float2 w2 = cmul(w1, w1);
        float2 w3 = cmul(w1, w2);
        int o = 4 * i;
        dst[SW(o)]     = b0;
        dst[SW(o + 1)] = cmul(b1, w1);
        dst[SW(o + 2)] = cmul(b2, w2);
        dst[SW(o + 3)] = cmul(b3, w3);
    }
}

// First inverse stage (L=1) fused with Hermitian repack.
__device__ __forceinline__ void r4_first_inv_repack(const float2* __restrict__ X,
                                                    float2* __restrict__ dst,
                                                    const float2* __restrict__ TW) {
    const int tid = threadIdx.x;
#pragma unroll
    for (int ii = 0; ii < 2; ++ii) {
        int i = tid + ii * NT;
        float2 z[4];
#pragma unroll
        for (int p = 0; p < 4; ++p) {
            int k = i + 512 * p;
            float2 xk = X[k];
            float2 xc = X[2048 - k]; xc.y = -xc.y;
            float2 fe = make_float2(0.5f * (xk.x + xc.x), 0.5f * (xk.y + xc.y));
            float2 d  = make_float2(0.5f * (xk.x - xc.x), 0.5f * (xk.y - xc.y));
            float2 fo = cmul(d, TW[k]);                         // * e^{+i 2pi k/4096}
            z[p] = make_float2(fe.x - fo.y, fe.y + fo.x);       // fe + i*fo
        }
        float2 t0 = make_float2(z[0].x + z[2].x, z[0].y + z[2].y);
        float2 t1 = make_float2(z[0].x - z[2].x, z[0].y - z[2].y);
        float2 t2 = make_float2(z[1].x + z[3].x, z[1].y + z[3].y);
        float2 t3 = make_float2(z[1].x - z[3].x, z[1].y - z[3].y);
        float2 b0 = make_float2(t0.x + t2.x, t0.y + t2.y);
        float2 b2 = make_float2(t0.x - t2.x, t0.y - t2.y);
        float2 b1 = make_float2(t1.x - t3.y, t1.y + t3.x);      // inverse: t1 + i t3
        float2 b3 = make_float2(t1.x + t3.y, t1.y - t3.x);
        float2 w1 = TW[2 * i];                                  // +i twiddles
        float2 w2 = cmul(w1, w1);
        float2 w3 = cmul(w1, w2);
        int o = 4 * i;
        dst[SW(o)]     = b0;
        dst[SW(o + 1)] = cmul(b1, w1);
        dst[SW(o + 2)] = cmul(b2, w2);
        dst[SW(o + 3)] = cmul(b3, w3);
    }
}

// ---------------------------------------------------------------------------
// Per-(b,c): rfft(4096) -> top-64 mask -> irfft(4096).
// Reads/writes the (B,S,C) layout directly at channel stride; cross-CTA L2
// reuse coalesces the DRAM traffic (32 channel-CTAs per 128B line).
// Shared layout (floats):
//   A  [2048 float2] @ 0      (swizzled ping buffer)
//   Bb [2052 float2] @ 4096   (swizzled pong buffer; X aliases it, identity idx)
// total 8200 floats = 32800 bytes
// ---------------------------------------------------------------------------
__global__ void __launch_bounds__(NT, 6) fft_topk_kernel(const float* __restrict__ in,
                                                         float* __restrict__ out) {
    extern __shared__ float sh[];
    float2* A  = (float2*)sh;
    float2* Bb = (float2*)(sh + 4096);
    float2* X  = Bb;                 // aliases Bb, identity-indexed (2049 entries)
    const float2* TW = g_tw;
    __shared__ unsigned ws[2][8];

    const int tid = threadIdx.x;
    const int b = blockIdx.x >> 7;          // blockIdx.x = b*128 + c
    const int c = blockIdx.x & 127;
    const float* gch = in  + (size_t)b * S_DIM * C_DIM + c;
    float*       och = out + (size_t)b * S_DIM * C_DIM + c;

    // ---- forward FFT: 5 radix-4 stages + twiddle-free radix-2 ----
    r4_first_fwd_gmem(gch, Bb, TW);      __syncthreads();
    r4_stage<4,   false>(Bb, A,  TW);    __syncthreads();
    r4_stage<16,  false>(A,  Bb, TW);    __syncthreads();
    r4_stage<64,  false>(Bb, A,  TW);    __syncthreads();
    r4_stage<256, false>(A,  Bb, TW);    __syncthreads();
    // radix-2, L=1024, twiddle-free: Bb -> A  (Z lives in A)
#pragma unroll
    for (int ii = 0; ii < 4; ++ii) {
        int i = tid + ii * NT;
        float2 a = Bb[SW(i)], b2 = Bb[SW(i + 1024)];
        A[SW(i)]        = make_float2(a.x + b2.x, a.y + b2.y);
        A[SW(i + 1024)] = make_float2(a.x - b2.x, a.y - b2.y);
    }
    __syncthreads();

    // ---- Hermitian unpack: X[k] (into Bb, identity idx), mag^2 bits ----
    unsigned mv[9];
#pragma unroll
    for (int q = 0; q < 9; ++q) mv[q] = 0u;
#pragma unroll
    for (int q = 0; q < 9; ++q) {
        int k = tid + q * NT;
        if (k < 2049) {
            int k1 = k & (N2 - 1);
            int k2 = (N2 - k) & (N2 - 1);
            float2 a  = A[SW(k1)];
            float2 bc = A[SW(k2)]; bc.y = -bc.y;
            float2 fe = make_float2(0.5f * (a.x + bc.x), 0.5f * (a.y + bc.y));
            float2 d  = make_float2(0.5f * (a.x - bc.x), 0.5f * (a.y - bc.y));
            float2 w  = (k == N2) ? make_float2(-1.0f, 0.0f)
                                  : make_float2(TW[k].x, -TW[k].y);
            float2 wd = cmul(w, d);
            float2 x = make_float2(fe.x + wd.y, fe.y - wd.x);  // fe - i*(w*d)
            X[k] = x;
            mv[q] = mag2u(x);
        }
    }
    __syncthreads();

    // ---- block max seed for the search ----
    {
        unsigned vm = 0;
#pragma unroll
        for (int q = 0; q < 9; ++q) vm = max(vm, mv[q]);
        vm = __reduce_max_sync(0xffffffffu, vm);
        if ((tid & 31) == 0) ws[1][tid >> 5] = vm;
    }
    __syncthreads();
    unsigned mx = 0;
#pragma unroll
    for (int w = 0; w < 8; ++w) mx = max(mx, ws[1][w]);

    // ---- binary search for the 64th-largest mag^2 (1 barrier / iter) ----
    unsigned lo = 0u, hi = mx + 1u, thr = 0u;
    bool exact = false;
    int it = 0;
    while (hi - lo > 1u) {
        unsigned mid = lo + ((hi - lo) >> 1);
        unsigned v = 0;
#pragma unroll
        for (int q = 0; q < 9; ++q) v += (mv[q] >= mid);
        v = __reduce_add_sync(0xffffffffu, v);
        if ((tid & 31) == 0) ws[it & 1][tid >> 5] = v;
        __syncthreads();
        unsigned cnt = 0;
#pragma unroll
        for (int w = 0; w < 8; ++w) cnt += ws[it & 1][w];
        if (cnt == TOPK) { thr = mid; exact = true; break; }
        if (cnt > TOPK) lo = mid; else hi = mid;
        ++it;
    }
    int need = 0;
    if (!exact) {
        thr = lo;
        unsigned v = 0;
#pragma unroll
        for (int q = 0; q < 9; ++q) v += (mv[q] > thr);
        v = __reduce_add_sync(0xffffffffu, v);
        if ((tid & 31) == 0) ws[(it + 1) & 1][tid >> 5] = v;
        __syncthreads();
        unsigned cnt = 0;
#pragma unroll
        for (int w = 0; w < 8; ++w) cnt += ws[(it + 1) & 1][w];
        need = TOPK - (int)cnt;   // ties at thr kept lowest-index-first
    }

    // ---- keep decisions first (X stable), then barrier, then zero ----
    unsigned keepmask = 0u;
#pragma unroll
    for (int q = 0; q < 9; ++q) {
        int k = tid + q * NT;
        if (k < 2049) {
            unsigned u = mv[q];
            bool keep;
            if (exact) {
                keep = (u >= thr);
            } else if (u > thr) {
                keep = true;
            } else if (u == thr) {
                int r = 0;
                for (int j = 0; j < k; ++j)
                    r += (mag2u(X[j]) == thr);
                keep = (r < need);
            } else {
                keep = false;
            }
            if (keep) keepmask |= (1u << q);
        }
    }
    __syncthreads();
#pragma unroll
    for (int q = 0; q < 9; ++q) {
        int k = tid + q * NT;
        if (k < 2049 && !(keepmask & (1u << q)))
            X[k] = make_float2(0.0f, 0.0f);
    }
    __syncthreads();

    // ---- inverse FFT: repack fused into first radix-4 stage ----
    r4_first_inv_repack(X, A, TW);       __syncthreads();
    r4_stage<4,   true>(A,  Bb, TW);     __syncthreads();
    r4_stage<16,  true>(Bb, A,  TW);     __syncthreads();
    r4_stage<64,  true>(A,  Bb, TW);     __syncthreads();
    r4_stage<256, true>(Bb, A,  TW);     __syncthreads();
    // radix-2, L=1024, twiddle-free, scaled, write straight to gmem (strided)
    const float sc = 1.0f / 2048.0f;
#pragma unroll
    for (int ii = 0; ii < 4; ++ii) {
        int i = tid + ii * NT;
        float2 a = A[SW(i)], b2 = A[SW(i + 1024)];
        float2 lo2 = make_float2((a.x + b2.x) * sc, (a.y + b2.y) * sc);
        float2 hi2 = make_float2((a.x - b2.x) * sc, (a.y - b2.y) * sc);
        och[(2 * i)          * C_DIM] = lo2.x;
        och[(2 * i + 1)      * C_DIM] = lo2.y;
        och[(2 * i + 2048)   * C_DIM] = hi2.x;
        och[(2 * i + 2049)   * C_DIM] = hi2.y;
    }
}

// ---------------------------------------------------------------------------
extern "C" void kernel_launch(void* const* d_in, const int* in_sizes, int n_in,
                              void* d_out, int out_size) {
    const float* ts = (const float*)d_in[0];
    float* out = (float*)d_out;

    const int smem_bytes = 32800;
    cudaFuncSetAttribute(fft_topk_kernel,
                         cudaFuncAttributeMaxDynamicSharedMemorySize, smem_bytes);

    init_tw_kernel<<<N2 / 256, 256>>>();
    fft_topk_kernel<<<B_DIM * C_DIM, NT, smem_bytes>>>(ts, out);
}

// round 7
// speedup vs baseline: 2.0920x; 2.0920x over previous
#include <cuda_runtime.h>
#include <math.h>

// Problem constants
#define B_DIM 64
#define S_DIM 4096
#define C_DIM 128
#define N2 2048          // half-length complex FFT size
#define NT 256
#define TOPK 64

// 128 MB scratch in (B, C, S) layout
__device__ float g_scratch[(size_t)B_DIM * C_DIM * S_DIM];
// Twiddle table in global: g_tw[t] = (cos(pi t/2048), sin(pi t/2048))
__device__ float2 g_tw[N2];

__device__ __forceinline__ float2 cmul(float2 a, float2 b) {
    return make_float2(a.x * b.x - a.y * b.y, a.x * b.y + a.y * b.x);
}
__device__ __forceinline__ float2 cadd(float2 a, float2 b) {
    return make_float2(a.x + b.x, a.y + b.y);
}
__device__ __forceinline__ float2 csub(float2 a, float2 b) {
    return make_float2(a.x - b.x, a.y - b.y);
}

// Bank swizzle: bijective on [0,2048); conflict-free for all Stockham
// radix-8 patterns used here (stride-8 scatter, blocked scatter, consecutive).
__device__ __forceinline__ int SW(int i) { return i ^ (i >> 3); }

// Bit-exact mag^2 (used for both ranking values and the tie re-check).
__device__ __forceinline__ unsigned mag2u(float2 x) {
    return __float_as_uint(__fadd_rn(__fmul_rn(x.x, x.x), __fmul_rn(x.y, x.y)));
}

// ---------------------------------------------------------------------------
__global__ void __launch_bounds__(256) init_tw_kernel() {
    int t = blockIdx.x * 256 + threadIdx.x;
    float s, c;
    sincospif((float)t * (1.0f / 2048.0f), &s, &c);
    g_tw[t] = make_float2(c, s);
}

// ---------------------------------------------------------------------------
// Transposes (proven ~45us each, near DRAM roofline)
// ---------------------------------------------------------------------------
__global__ void __launch_bounds__(256) transpose_in_kernel(const float* __restrict__ in) {
    __shared__ float tile[32][33];
    const int b = blockIdx.z;
    const int c0 = blockIdx.x * 32;
    const int r0 = blockIdx.y * 32;
    const int tx = threadIdx.x, ty = threadIdx.y;
    const float* inb = in + (size_t)b * S_DIM * C_DIM;
    float* outb = g_scratch + (size_t)b * S_DIM * C_DIM;
#pragma unroll
    for (int j = 0; j < 32; j += 8)
        tile[ty + j][tx] = inb[(size_t)(r0 + ty + j) * C_DIM + (c0 + tx)];
    __syncthreads();
#pragma unroll
    for (int j = 0; j < 32; j += 8)
        outb[(size_t)(c0 + ty + j) * S_DIM + (r0 + tx)] = tile[tx][ty + j];
}

__global__ void __launch_bounds__(256) transpose_out_kernel(float* __restrict__ out) {
    __shared__ float tile[32][33];
    const int b = blockIdx.z;
    const int c0 = blockIdx.x * 32;
    const int r0 = blockIdx.y * 32;
    const int tx = threadIdx.x, ty = threadIdx.y;
    const float* inb = g_scratch + (size_t)b * S_DIM * C_DIM;
    float* outb = out + (size_t)b * S_DIM * C_DIM;
#pragma unroll
    for (int j = 0; j < 32; j += 8)
        tile[ty + j][tx] = inb[(size_t)(r0 + ty + j) * S_DIM + (c0 + tx)];
    __syncthreads();
#pragma unroll
    for (int j = 0; j < 32; j += 8)
        outb[(size_t)(c0 + ty + j) * C_DIM + (r0 + tx)] = tile[tx][ty + j];
}

// ---------------------------------------------------------------------------
// Radix-8 butterfly. Forward: omega = e^{-2pi i/8}; inverse: conjugate.
// ---------------------------------------------------------------------------
template<bool INV>
__device__ __forceinline__ void bfly8(const float2* a, float2* b) {
    const float r = 0.70710678118654752440f;
    float2 s0 = cadd(a[0], a[4]), s1 = csub(a[0], a[4]);
    float2 s2 = cadd(a[2], a[6]), s3 = csub(a[2], a[6]);
    float2 s4 = cadd(a[1], a[5]), s5 = csub(a[1], a[5]);
    float2 s6 = cadd(a[3], a[7]), s7 = csub(a[3], a[7]);
    float2 E0 = cadd(s0, s2), E2 = csub(s0, s2);
    float2 O0 = cadd(s4, s6), O2 = csub(s4, s6);
    float2 E1, E3, O1, O3;
    if (!INV) {
        E1 = make_float2(s1.x + s3.y, s1.y - s3.x);   // s1 - i s3
        E3 = make_float2(s1.x - s3.y, s1.y + s3.x);
        O1 = make_float2(s5.x + s7.y, s5.y - s7.x);
        O3 = make_float2(s5.x - s7.y, s5.y + s7.x);
    } else {
        E1 = make_float2(s1.x - s3.y, s1.y + s3.x);   // s1 + i s3
        E3 = make_float2(s1.x + s3.y, s1.y - s3.x);
        O1 = make_float2(s5.x - s7.y, s5.y + s7.x);
        O3 = make_float2(s5.x + s7.y, s5.y - s7.x);
    }
    b[0] = cadd(E0, O0);
    b[4] = csub(E0, O0);
    float2 w1O, w3O;
    if (!INV) {
        w1O = make_float2(r * (O1.x + O1.y), r * (O1.y - O1.x));   // e^{-i pi/4} O1
        w3O = make_float2(r * (O3.y - O3.x), -r * (O3.x + O3.y));  // e^{-3i pi/4} O3
        b[2] = make_float2(E2.x + O2.y, E2.y - O2.x);              // E2 - i O2
        b[6] = make_float2(E2.x - O2.y, E2.y + O2.x);
    } else {
        w1O = make_float2(r * (O1.x - O1.y), r * (O1.x + O1.y));   // e^{+i pi/4} O1
        w3O = make_float2(-r * (O3.x + O3.y), r * (O3.x - O3.y));  // e^{+3i pi/4} O3
        b[2] = make_float2(E2.x - O2.y, E2.y + O2.x);              // E2 + i O2
        b[6] = make_float2(E2.x + O2.y, E2.y - O2.x);
    }
    b[1] = cadd(E1, w1O);
    b[5] = csub(E1, w1O);
    b[3] = cadd(E3, w3O);
    b[7] = csub(E3, w3O);
}

// Generic radix-8 Stockham stage, smem->smem, swizzled, one butterfly/thread.
template<int L, bool INV>
__device__ __forceinline__ void r8_stage(const float2* __restrict__ src,
                                         float2* __restrict__ dst,
                                         const float2* __restrict__ TW) {
    const int i = threadIdx.x;           // 256 butterflies
    const int k = i & (L - 1);
    const int u = i - k;
    float2 a[8], b[8];
#pragma unroll
    for (int m = 0; m < 8; ++m) a[m] = src[SW(i + 256 * m)];
    bfly8<INV>(a, b);
    float2 w1 = TW[2 * u];
    if (!INV) w1.y = -w1.y;
    const int o = 8 * u + k;
    dst[SW(o)] = b[0];
    float2 w = w1;
#pragma unroll
    for (int q = 1; q < 8; ++q) {
        dst[SW(o + q * L)] = cmul(b[q], w);
        w = cmul(w, w1);
    }
}

// First forward radix-8 stage (L=1), reading coalesced from global row.
__device__ __forceinline__ void r8_first_fwd(const float2* __restrict__ g,
                                             float2* __restrict__ dst,
                                             const float2* __restrict__ TW) {
    const int i = threadIdx.x;
    float2 a[8], b[8];
#pragma unroll
    for (int m = 0; m < 8; ++m) a[m] = g[i + 256 * m];
    bfly8<false>(a, b);
    float2 w1 = TW[2 * i]; w1.y = -w1.y;
    const int o = 8 * i;
    dst[SW(o)] = b[0];
    float2 w = w1;
#pragma unroll
    for (int q = 1; q < 8; ++q) {
        dst[SW(o + q)] = cmul(b[q], w);
        w = cmul(w, w1);
    }
}

// ---------------------------------------------------------------------------
// Per-row FFT + top-k + inverse FFT.
// Shared layout (dynamic, floats):
//   A  [2048 float2] @ 0      swizzled ping buffer
//   Bb [2049 float2] @ 4096   swizzled pong buffer; X aliases it identity-idx
// = 8194 floats = 32776 bytes.  Static: ws[2][8], kb[65].
// ---------------------------------------------------------------------------
__global__ void __launch_bounds__(NT, 5) fft_topk_kernel() {
    extern __shared__ float sh[];
    float2* A  = (float2*)sh;
    float2* Bb = (float2*)(sh + 4096);
    float2* X  = Bb;                 // identity-indexed (2049 entries)
    const float2* TW = g_tw;
    __shared__ unsigned ws[2][8];
    __shared__ unsigned kb[65];      // keep bitmask, 2049 bits

    const int tid = threadIdx.x;
    float* rowp = g_scratch + (size_t)blockIdx.x * S_DIM;
    const float2* gz = (const float2*)rowp;

    // ---- forward FFT: 3 radix-8 stages + twiddle-free radix-4 ----
    r8_first_fwd(gz, Bb, TW);        __syncthreads();
    r8_stage<8,  false>(Bb, A,  TW); __syncthreads();
    r8_stage<64, false>(A,  Bb, TW); __syncthreads();
    // final radix-4, L=512, twiddle-free: Bb -> A
#pragma unroll
    for (int ii = 0; ii < 2; ++ii) {
        int i = tid + ii * NT;
        float2 a0 = Bb[SW(i)];
        float2 a1 = Bb[SW(i + 512)];
        float2 a2 = Bb[SW(i + 1024)];
        float2 a3 = Bb[SW(i + 1536)];
        float2 t0 = cadd(a0, a2), t1 = csub(a0, a2);
        float2 t2 = cadd(a1, a3), t3 = csub(a1, a3);
        A[SW(i)]         = cadd(t0, t2);
        A[SW(i + 512)]   = make_float2(t1.x + t3.y, t1.y - t3.x);  // t1 - i t3
        A[SW(i + 1024)]  = csub(t0, t2);
        A[SW(i + 1536)]  = make_float2(t1.x - t3.y, t1.y + t3.x);  // t1 + i t3
    }
    __syncthreads();

    // ---- Hermitian unpack: X[k] into Bb (identity idx), mag^2 bits ----
    unsigned mv[9];
#pragma unroll
    for (int q = 0; q < 9; ++q) mv[q] = 0u;
#pragma unroll
    for (int q = 0; q < 9; ++q) {
        int k = tid + q * NT;
        if (k < 2049) {
            int k1 = k & (N2 - 1);
            int k2 = (N2 - k) & (N2 - 1);
            float2 a  = A[SW(k1)];
            float2 bc = A[SW(k2)]; bc.y = -bc.y;
            float2 fe = make_float2(0.5f * (a.x + bc.x), 0.5f * (a.y + bc.y));
            float2 d  = make_float2(0.5f * (a.x - bc.x), 0.5f * (a.y - bc.y));
            float2 w  = (k == N2) ? make_float2(-1.0f, 0.0f)
                                  : make_float2(TW[k].x, -TW[k].y);
            float2 wd = cmul(w, d);
            float2 x = make_float2(fe.x + wd.y, fe.y - wd.x);  // fe - i*(w*d)
            X[k] = x;
            mv[q] = mag2u(x);
        }
    }
    __syncthreads();

    // ---- block max seed ----
    {
        unsigned vm = 0;
#pragma unroll
        for (int q = 0; q < 9; ++q) vm = max(vm, mv[q]);
        vm = __reduce_max_sync(0xffffffffu, vm);
        if ((tid & 31) == 0) ws[1][tid >> 5] = vm;
    }
    __syncthreads();
    unsigned mx = 0;
#pragma unroll
    for (int w = 0; w < 8; ++w) mx = max(mx, ws[1][w]);

    // ---- binary search for the 64th-largest mag^2 (1 barrier / iter) ----
    unsigned lo = 0u, hi = mx + 1u, thr = 0u;
    bool exact = false;
    int it = 0;
    while (hi - lo > 1u) {
        unsigned mid = lo + ((hi - lo) >> 1);
        unsigned v = 0;
#pragma unroll
        for (int q = 0; q < 9; ++q) v += (mv[q] >= mid);
        v = __reduce_add_sync(0xffffffffu, v);
        if ((tid & 31) == 0) ws[it & 1][tid >> 5] = v;
        __syncthreads();
        unsigned cnt = 0;
#pragma unroll
        for (int w = 0; w < 8; ++w) cnt += ws[it & 1][w];
        if (cnt == TOPK) { thr = mid; exact = true; break; }
        if (cnt > TOPK) lo = mid; else hi = mid;
        ++it;
    }
    int need = 0;
    if (!exact) {
        thr = lo;
        unsigned v = 0;
#pragma unroll
        for (int q = 0; q < 9; ++q) v += (mv[q] > thr);
        v = __reduce_add_sync(0xffffffffu, v);
        if ((tid & 31) == 0) ws[(it + 1) & 1][tid >> 5] = v;
        __syncthreads();
        unsigned cnt = 0;
#pragma unroll
        for (int w = 0; w < 8; ++w) cnt += ws[(it + 1) & 1][w];
        need = TOPK - (int)cnt;   // ties at thr kept lowest-index-first
    }

    // ---- keep decisions -> ballot bitmask (no X modification, no race) ----
#pragma unroll
    for (int q = 0; q < 9; ++q) {
        int k = tid + q * NT;
        bool keep = false;
        if (k < 2049) {
            unsigned u = mv[q];
            if (exact) {
                keep = (u >= thr);
            } else if (u > thr) {
                keep = true;
            } else if (u == thr) {
                int r = 0;
                for (int j = 0; j < k; ++j)
                    r += (mag2u(X[j]) == thr);
                keep = (r < need);
            }
        }
        unsigned bal = __ballot_sync(0xffffffffu, keep);
        int word = (tid >> 5) + 8 * q;
        if ((tid & 31) == 0 && word <= 64) kb[word] = bal;
    }
    __syncthreads();

    // ---- inverse FFT: Hermitian repack (masked) fused into first r8 stage ----
    {
        const int i = tid;
        float2 z[8], b[8];
#pragma unroll
        for (int m = 0; m < 8; ++m) {
            int k = i + 256 * m;
            int kc = 2048 - k;
            float2 xk = X[k];
            if (!((kb[k >> 5] >> (k & 31)) & 1u)) xk = make_float2(0.0f, 0.0f);
            float2 xc = X[kc];
            if (!((kb[kc >> 5] >> (kc & 31)) & 1u)) xc = make_float2(0.0f, 0.0f);
            xc.y = -xc.y;
            float2 fe = make_float2(0.5f * (xk.x + xc.x), 0.5f * (xk.y + xc.y));
            float2 d  = make_float2(0.5f * (xk.x - xc.x), 0.5f * (xk.y - xc.y));
            float2 fo = cmul(d, TW[k]);                     // * e^{+i 2pi k/4096}
            z[m] = make_float2(fe.x - fo.y, fe.y + fo.x);   // fe + i*fo
        }
        bfly8<true>(z, b);
        float2 w1 = TW[2 * i];
        const int o = 8 * i;
        A[SW(o)] = b[0];
        float2 w = w1;
#pragma unroll
        for (int q = 1; q < 8; ++q) {
            A[SW(o + q)] = cmul(b[q], w);
            w = cmul(w, w1);
        }
    }
    __syncthreads();
    r8_stage<8,  true>(A,  Bb, TW);  __syncthreads();
    r8_stage<64, true>(Bb, A,  TW);  __syncthreads();
    // final radix-4, L=512, twiddle-free, scaled, straight to global
    const float sc = 1.0f / 2048.0f;
    float2* go = (float2*)rowp;
#pragma unroll
    for (int ii = 0; ii < 2; ++ii) {
        int i = tid + ii * NT;
        float2 a0 = A[SW(i)];
        float2 a1 = A[SW(i + 512)];
        float2 a2 = A[SW(i + 1024)];
        float2 a3 = A[SW(i + 1536)];
        float2 t0 = cadd(a0, a2), t1 = csub(a0, a2);
        float2 t2 = cadd(a1, a3), t3 = csub(a1, a3);
        float2 b0 = cadd(t0, t2);
        float2 b1 = make_float2(t1.x - t3.y, t1.y + t3.x);  // t1 + i t3 (inverse)
        float2 b2 = csub(t0, t2);
        float2 b3 = make_float2(t1.x + t3.y, t1.y - t3.x);
        go[i]        = make_float2(b0.x * sc, b0.y * sc);
        go[i + 512]  = make_float2(b1.x * sc, b1.y * sc);
        go[i + 1024] = make_float2(b2.x * sc, b2.y * sc);
        go[i + 1536] = make_float2(b3.x * sc, b3.y * sc);
    }
}

// ---------------------------------------------------------------------------
extern "C" void kernel_launch(void* const* d_in, const int* in_sizes, int n_in,
                              void* d_out, int out_size) {
    const float* ts = (const float*)d_in[0];
    float* out = (float*)d_out;

    const int smem_bytes = 32800;
    cudaFuncSetAttribute(fft_topk_kernel,
                         cudaFuncAttributeMaxDynamicSharedMemorySize, smem_bytes);

    dim3 tblk(32, 8);
    init_tw_kernel<<<N2 / 256, 256>>>();
    transpose_in_kernel<<<dim3(C_DIM / 32, S_DIM / 32, B_DIM), tblk>>>(ts);
    fft_topk_kernel<<<B_DIM * C_DIM, NT, smem_bytes>>>();
    transpose_out_kernel<<<dim3(S_DIM / 32, C_DIM / 32, B_DIM), tblk>>>(out);
}